// round 15
// baseline (speedup 1.0000x reference)
#include <cuda_runtime.h>
#include <math.h>

#define Bn 512
#define Hn 1024
#define Sn 1024
#define Dn 128
#define Kn 32

// Output layout: [read (B*D)] [new_memory (B*S*D)] [weights (B*S)]
#define READ_OFF 0
#define MEM_OFF  (Bn*Dn)
#define W_OFF    (Bn*Dn + (size_t)Bn*Sn*Dn)

typedef unsigned long long u64;

// Packed fp32x2 FMA (Blackwell): d = a*b + c on both 32-bit halves.
__device__ __forceinline__ u64 fma2(u64 a, u64 b, u64 c) {
    u64 d;
    asm("fma.rn.f32x2 %0, %1, %2, %3;" : "=l"(d) : "l"(a), "l"(b), "l"(c));
    return d;
}
__device__ __forceinline__ u64 dup2(float x) {
    u64 d;
    asm("mov.b64 %0, {%1, %1};" : "=l"(d) : "f"(x));
    return d;
}
__device__ __forceinline__ float2 unpack2(u64 v) {
    float lo, hi;
    asm("mov.b64 {%0, %1}, %2;" : "=f"(lo), "=f"(hi) : "l"(v));
    return make_float2(lo, hi);
}

// Scratch (no allocation allowed -> device globals)
__device__ float4 g_query[Bn * (Dn/4)];   // [B][32] float4
__device__ float4 g_value[Bn * (Dn/4)];
__device__ float  g_logits[Bn * Sn];
__device__ float  g_gate[Bn];
__device__ int    g_ti[Bn * Kn];
__device__ float  g_tw[Bn * Kn];
__device__ float  g_gl[Bn];     // latent . write_gate_w[0:H]
__device__ float  g_gd[Bn];     // latent . dmd_proj_w[0:H]
__device__ float  g_gp[Bn];     // latent . phase_proj_w  (complete)
__device__ int    g_lg_done;    // logits completion counter

// ---------------------------------------------------------------------------
// K1: query/value GEMM with packed f32x2 FMA (+ gate partials).
// Also resets g_lg_done (qv -> logits edge is fully serialized).
// ---------------------------------------------------------------------------
__global__ __launch_bounds__(256, 3)
void qv_kernel(const float* __restrict__ latent,
               const float* __restrict__ Wq, const float* __restrict__ bq,
               const float* __restrict__ Wv, const float* __restrict__ bv,
               const float* __restrict__ wg, const float* __restrict__ wd,
               const float* __restrict__ wp)
{
    __shared__ __align__(16) float4 smem[1024];   // 16 KB

    if (blockIdx.x == 0 && blockIdx.y == 0 && threadIdx.x == 0) g_lg_done = 0;

    const int b0 = blockIdx.x * 4;
    const int mat = blockIdx.y;
    const ulonglong2* W2 = (const ulonglong2*)(mat ? Wv : Wq);
    const float4* bias4  = (const float4*)(mat ? bv : bq);
    float4*       out4   = mat ? g_value : g_query;

    const int tid = threadIdx.x;
    const int dq  = tid & 31;
    const int hs  = tid >> 5;

    {
        const float4* src = (const float4*)(latent + (size_t)b0 * Hn);
        #pragma unroll
        for (int i = 0; i < 4; i++) smem[tid + i * 256] = src[tid + i * 256];
    }
    __syncthreads();

    u64 aLo[4], aHi[4];
    #pragma unroll
    for (int j = 0; j < 4; j++) { aLo[j] = 0ull; aHi[j] = 0ull; }

    const int hbase = hs * 128;
    #pragma unroll 4
    for (int c = 0; c < 32; c++) {
        const int h0 = hbase + c * 4;
        ulonglong2 w0 = W2[(size_t)(h0 + 0) * 32 + dq];
        ulonglong2 w1 = W2[(size_t)(h0 + 1) * 32 + dq];
        ulonglong2 w2 = W2[(size_t)(h0 + 2) * 32 + dq];
        ulonglong2 w3 = W2[(size_t)(h0 + 3) * 32 + dq];
        #pragma unroll
        for (int j = 0; j < 4; j++) {
            float4 lf = smem[j * 256 + hs * 32 + c];   // broadcast
            u64 lx = dup2(lf.x), ly = dup2(lf.y), lz = dup2(lf.z), lw = dup2(lf.w);
            aLo[j] = fma2(lx, w0.x, aLo[j]);
            aLo[j] = fma2(ly, w1.x, aLo[j]);
            aLo[j] = fma2(lz, w2.x, aLo[j]);
            aLo[j] = fma2(lw, w3.x, aLo[j]);
            aHi[j] = fma2(lx, w0.y, aHi[j]);
            aHi[j] = fma2(ly, w1.y, aHi[j]);
            aHi[j] = fma2(lz, w2.y, aHi[j]);
            aHi[j] = fma2(lw, w3.y, aHi[j]);
        }
    }

    if (mat == 0 && tid < 128) {
        const int wrp  = tid >> 5;
        const int lane = tid & 31;
        const float* latf = (const float*)smem + wrp * 1024;
        float pg = 0.f, pd = 0.f, pp = 0.f;
        #pragma unroll 8
        for (int i = lane; i < Hn; i += 32) {
            float x = latf[i];
            pg += x * wg[i];
            pd += x * wd[i];
            pp += x * wp[i];
        }
        #pragma unroll
        for (int o = 16; o; o >>= 1) {
            pg += __shfl_xor_sync(0xffffffffu, pg, o);
            pd += __shfl_xor_sync(0xffffffffu, pd, o);
            pp += __shfl_xor_sync(0xffffffffu, pp, o);
        }
        if (lane == 0) {
            g_gl[b0 + wrp] = pg;
            g_gd[b0 + wrp] = pd;
            g_gp[b0 + wrp] = pp;
        }
    }
    __syncthreads();

    #pragma unroll
    for (int j = 0; j < 4; j++) {
        float2 lo = unpack2(aLo[j]), hi = unpack2(aHi[j]);
        smem[hs * 128 + j * 32 + dq] = make_float4(lo.x, lo.y, hi.x, hi.y);
    }
    __syncthreads();

    if (tid < 128) {
        const int j2  = tid >> 5;
        const int dq2 = tid & 31;
        float4 s = make_float4(0.f, 0.f, 0.f, 0.f);
        #pragma unroll
        for (int h = 0; h < 8; h++) {
            float4 v = smem[h * 128 + j2 * 32 + dq2];
            s.x += v.x; s.y += v.y; s.z += v.z; s.w += v.w;
        }
        float4 bb = bias4[dq2];
        s.x += bb.x; s.y += bb.y; s.z += bb.z; s.w += bb.w;
        out4[(size_t)(b0 + j2) * 32 + dq2] = s;
    }
}

// ---------------------------------------------------------------------------
// K2: logits = query @ key^T, packed f32x2. Fires launch_dependents at START
// (releases batch early); publishes completion via g_lg_done at the end.
// ---------------------------------------------------------------------------
#define L_SMEM_BYTES ((32 + 64) * 33 * (int)sizeof(float4))

__global__ __launch_bounds__(256, 2)
void logits_kernel(const float* __restrict__ key)
{
    asm volatile("griddepcontrol.launch_dependents;");   // release batch now

    extern __shared__ float4 dyn[];
    float4* qs = dyn;             // [32][33]
    float4* ks = dyn + 32 * 33;   // [64][33]

    const int b0 = blockIdx.x * 32;
    const int s0 = blockIdx.y * 64;
    const int tid = threadIdx.x;

    const float4* q4 = g_query;
    const float4* k4 = (const float4*)key;
    #pragma unroll
    for (int i = tid; i < 32 * 32; i += 256) {
        int r = i >> 5, c = i & 31;
        qs[r * 33 + c] = q4[(size_t)(b0 + r) * 32 + c];
    }
    #pragma unroll
    for (int i = tid; i < 64 * 32; i += 256) {
        int r = i >> 5, c = i & 31;
        ks[r * 33 + c] = k4[(size_t)(s0 + r) * 32 + c];
    }
    __syncthreads();

    const ulonglong2* qs2 = (const ulonglong2*)qs;
    const ulonglong2* ks2 = (const ulonglong2*)ks;

    const int tx = tid & 15;
    const int ty = tid >> 4;

    u64 accp[2][4];
    #pragma unroll
    for (int i = 0; i < 2; i++)
        #pragma unroll
        for (int j = 0; j < 4; j++) accp[i][j] = 0ull;

    #pragma unroll 8
    for (int c = 0; c < 32; c++) {
        ulonglong2 qv2[2], kv2[4];
        #pragma unroll
        for (int i = 0; i < 2; i++) qv2[i] = qs2[(ty + 16 * i) * 33 + c];
        #pragma unroll
        for (int j = 0; j < 4; j++) kv2[j] = ks2[(tx + 16 * j) * 33 + c];
        #pragma unroll
        for (int i = 0; i < 2; i++)
            #pragma unroll
            for (int j = 0; j < 4; j++) {
                accp[i][j] = fma2(qv2[i].x, kv2[j].x, accp[i][j]);
                accp[i][j] = fma2(qv2[i].y, kv2[j].y, accp[i][j]);
            }
    }

    #pragma unroll
    for (int i = 0; i < 2; i++)
        #pragma unroll
        for (int j = 0; j < 4; j++) {
            float2 p = unpack2(accp[i][j]);
            g_logits[(size_t)(b0 + ty + 16 * i) * Sn + s0 + tx + 16 * j] = p.x + p.y;
        }

    // publish completion
    __threadfence();
    __syncthreads();
    if (tid == 0) atomicAdd(&g_lg_done, 1);
}

// ---------------------------------------------------------------------------
// K3 (PSS secondary of logits): fires launch_dependents FIRST (releases the
// copy at ~logits start), zeroes its weights row, spin-waits logits' flag,
// then top-32/softmax/read/gate. Stashes ti/tw for fixup.
// ---------------------------------------------------------------------------
__global__ __launch_bounds__(256, 4)
void batch_kernel(const float* __restrict__ memory,
                  const float* __restrict__ wg, const float* __restrict__ bg,
                  const float* __restrict__ wd, const float* __restrict__ bd,
                  const float* __restrict__ bp,
                  float* __restrict__ out)
{
    asm volatile("griddepcontrol.launch_dependents;");   // release the copy

    __shared__ __align__(16) float sl[Sn];
    __shared__ __align__(16) float rd[Dn];
    __shared__ int   s_flag;
    __shared__ int   ti[Kn];
    __shared__ float tw[Kn];

    const int b    = blockIdx.x;
    const int tid  = threadIdx.x;
    const int lane = tid & 31;

    // independent preamble: zero the weights row
    float* wout = out + W_OFF + (size_t)b * Sn;
    for (int i = tid; i < Sn / 4; i += 256)
        ((float4*)wout)[i] = make_float4(0.f, 0.f, 0.f, 0.f);

    // wait for logits completion (block-consistent double-barrier poll)
    for (;;) {
        if (tid == 0) s_flag = (atomicAdd(&g_lg_done, 0) >= (Bn / 32) * (Sn / 64));
        __syncthreads();
        int f = s_flag;
        __syncthreads();
        if (f) break;
        __nanosleep(100);
    }
    __threadfence();

    for (int i = tid; i < Sn; i += 256) sl[i] = g_logits[(size_t)b * Sn + i];
    __syncthreads();

    if (tid < 32) {
        for (int it = 0; it < Kn; it++) {
            float bv = -1e30f; int bi = 0;
            #pragma unroll
            for (int j = 0; j < 32; j++) {
                float v = sl[lane + 32 * j];
                if (v > bv) { bv = v; bi = lane + 32 * j; }
            }
            #pragma unroll
            for (int o = 16; o; o >>= 1) {
                float ov = __shfl_xor_sync(0xffffffffu, bv, o);
                int   oi = __shfl_xor_sync(0xffffffffu, bi, o);
                if (ov > bv || (ov == bv && oi < bi)) { bv = ov; bi = oi; }
            }
            if ((bi & 31) == lane) sl[bi] = -1e30f;
            if (lane == 0) { ti[it] = bi; tw[it] = bv; }
            __syncwarp();
        }
        float m = tw[0];
        float e = __expf(tw[lane] - m);
        float s = e;
        #pragma unroll
        for (int o = 16; o; o >>= 1) s += __shfl_xor_sync(0xffffffffu, s, o);
        float wgt = e / s;
        tw[lane] = wgt;
        g_ti[b * Kn + lane] = ti[lane];
        g_tw[b * Kn + lane] = wgt;
        __syncwarp();
    }
    __syncthreads();

    if (tid < Kn) wout[ti[tid]] = tw[tid];

    if (tid < Dn) {
        float acc = 0.f;
        #pragma unroll 8
        for (int k = 0; k < Kn; k++)
            acc += tw[k] * memory[((size_t)b * Sn + ti[k]) * Dn + tid];
        out[READ_OFF + (size_t)b * Dn + tid] = acc;
        rd[tid] = acc;
    }
    __syncthreads();

    if (tid < 32) {
        float4 x4 = ((const float4*)rd)[lane];
        const float4* wg4 = (const float4*)(wg + Hn);
        const float4* wd4 = (const float4*)(wd + Hn);
        float4 a = wg4[lane], d = wd4[lane];
        float pg = x4.x*a.x + x4.y*a.y + x4.z*a.z + x4.w*a.w;
        float pd = x4.x*d.x + x4.y*d.y + x4.z*d.z + x4.w*d.w;
        #pragma unroll
        for (int o = 16; o; o >>= 1) {
            pg += __shfl_xor_sync(0xffffffffu, pg, o);
            pd += __shfl_xor_sync(0xffffffffu, pd, o);
        }
        if (lane == 0) {
            float G  = g_gl[b] + pg;
            float Dv = g_gd[b] + pd;
            float P  = g_gp[b];
            float gate = 1.f / (1.f + __expf(-(G + bg[0])));
            float dmd  = tanhf(Dv + bd[0]);
            gate = gate * (0.75f + 0.5f * (dmd + 1.0f) * 0.5f);
            gate = fminf(fmaxf(gate, 0.f), 1.f);
            float ph = P + bp[0];
            gate *= 0.5f * (1.f + cosf(ph));
            g_gate[b] = gate;
        }
    }
}

// ---------------------------------------------------------------------------
// K4 (PSS secondary of batch): pure 256 MB streaming copy. Independent.
// ---------------------------------------------------------------------------
__global__ __launch_bounds__(256, 8)
void pure_copy_kernel(const float4* __restrict__ src, float4* __restrict__ dst)
{
    size_t base = (size_t)blockIdx.x * 1024 + threadIdx.x;
    #pragma unroll
    for (int j = 0; j < 4; j++) {
        size_t g = base + (size_t)j * 256;
        __stcs(&dst[g], __ldcs(&src[g]));
    }
}

// ---------------------------------------------------------------------------
// K5: blend the 32 top-k rows per batch. NORMAL launch: serializes after ALL
// prior stream work (batch and copy).
// ---------------------------------------------------------------------------
__global__ __launch_bounds__(256, 8)
void fixup_kernel(const float4* __restrict__ mem4, float* __restrict__ out)
{
    __shared__ int   ti[Kn];
    __shared__ float gw[Kn];

    const int b   = blockIdx.x;
    const int tid = threadIdx.x;

    if (tid < Kn) {
        ti[tid] = g_ti[b * Kn + tid];
        gw[tid] = g_gate[b] * g_tw[b * Kn + tid];
    }
    __syncthreads();

    float4* dst = (float4*)(out + MEM_OFF);

    #pragma unroll
    for (int i = 0; i < 4; i++) {
        int idx = tid + i * 256;          // 0..1023
        int r   = idx >> 5;               // topk slot
        int q   = idx & 31;               // quad in row
        int s   = ti[r];
        float w = gw[r];
        size_t g = ((size_t)b * Sn + s) * 32 + q;
        float4 m = mem4[g];
        float4 v = g_value[(size_t)b * 32 + q];
        m.x += w * (v.x - m.x);
        m.y += w * (v.y - m.y);
        m.z += w * (v.z - m.z);
        m.w += w * (v.w - m.w);
        dst[g] = m;
    }
}

// ---------------------------------------------------------------------------
extern "C" void kernel_launch(void* const* d_in, const int* in_sizes, int n_in,
                              void* d_out, int out_size)
{
    const float* latent    = (const float*)d_in[0];
    const float* memory    = (const float*)d_in[1];
    const float* rq_w      = (const float*)d_in[2];
    const float* rq_b      = (const float*)d_in[3];
    const float* mem_key   = (const float*)d_in[4];
    const float* wg_w      = (const float*)d_in[5];
    const float* wg_b      = (const float*)d_in[6];
    const float* wd_w      = (const float*)d_in[7];
    const float* wd_b      = (const float*)d_in[8];
    const float* wp_w      = (const float*)d_in[9];
    const float* wp_b      = (const float*)d_in[10];
    const float* wv_w      = (const float*)d_in[11];
    const float* wv_b      = (const float*)d_in[12];
    float* out = (float*)d_out;

    cudaFuncSetAttribute(logits_kernel,
                         cudaFuncAttributeMaxDynamicSharedMemorySize, L_SMEM_BYTES);

    qv_kernel<<<dim3(Bn / 4, 2), 256>>>(latent, rq_w, rq_b, wv_w, wv_b,
                                        wg_w, wd_w, wp_w);
    logits_kernel<<<dim3(Bn / 32, Sn / 64), 256, L_SMEM_BYTES>>>(mem_key);

    // batch: PSS secondary of logits (launches at logits' first instruction)
    {
        cudaLaunchConfig_t cfg = {};
        cfg.gridDim  = dim3(Bn);
        cfg.blockDim = dim3(256);
        cfg.stream = 0;
        cudaLaunchAttribute attr[1];
        attr[0].id = cudaLaunchAttributeProgrammaticStreamSerialization;
        attr[0].val.programmaticStreamSerializationAllowed = 1;
        cfg.attrs = attr;
        cfg.numAttrs = 1;
        cudaError_t e = cudaLaunchKernelEx(&cfg, batch_kernel, memory,
                                           wg_w, wg_b, wd_w, wd_b, wp_b, out);
        if (e != cudaSuccess)
            batch_kernel<<<Bn, 256>>>(memory, wg_w, wg_b, wd_w, wd_b, wp_b, out);
    }

    // copy: PSS secondary of batch (launches at batch's first instruction)
    {
        const float4* src = (const float4*)memory;
        float4*       dst = (float4*)(out + MEM_OFF);
        cudaLaunchConfig_t cfg = {};
        cfg.gridDim  = dim3((Bn * Sn * Dn / 4) / 1024);
        cfg.blockDim = dim3(256);
        cfg.stream = 0;
        cudaLaunchAttribute attr[1];
        attr[0].id = cudaLaunchAttributeProgrammaticStreamSerialization;
        attr[0].val.programmaticStreamSerializationAllowed = 1;
        cfg.attrs = attr;
        cfg.numAttrs = 1;
        cudaError_t e = cudaLaunchKernelEx(&cfg, pure_copy_kernel, src, dst);
        if (e != cudaSuccess)
            pure_copy_kernel<<<(Bn * Sn * Dn / 4) / 1024, 256>>>(src, dst);
    }

    fixup_kernel<<<Bn, 256>>>((const float4*)memory, out);
}

// round 16
// speedup vs baseline: 1.0158x; 1.0158x over previous
#include <cuda_runtime.h>
#include <math.h>

#define Bn 512
#define Hn 1024
#define Sn 1024
#define Dn 128
#define Kn 32

// Output layout: [read (B*D)] [new_memory (B*S*D)] [weights (B*S)]
#define READ_OFF 0
#define MEM_OFF  (Bn*Dn)
#define W_OFF    (Bn*Dn + (size_t)Bn*Sn*Dn)

typedef unsigned long long u64;

// Packed fp32x2 FMA (Blackwell): d = a*b + c on both 32-bit halves.
__device__ __forceinline__ u64 fma2(u64 a, u64 b, u64 c) {
    u64 d;
    asm("fma.rn.f32x2 %0, %1, %2, %3;" : "=l"(d) : "l"(a), "l"(b), "l"(c));
    return d;
}
__device__ __forceinline__ u64 dup2(float x) {
    u64 d;
    asm("mov.b64 %0, {%1, %1};" : "=l"(d) : "f"(x));
    return d;
}
__device__ __forceinline__ float2 unpack2(u64 v) {
    float lo, hi;
    asm("mov.b64 {%0, %1}, %2;" : "=f"(lo), "=f"(hi) : "l"(v));
    return make_float2(lo, hi);
}

// Scratch (no allocation allowed -> device globals)
__device__ float4 g_query[Bn * (Dn/4)];   // [B][32] float4
__device__ float4 g_value[Bn * (Dn/4)];
__device__ float  g_logits[Bn * Sn];
__device__ float  g_gate[Bn];
__device__ int    g_ti[Bn * Kn];
__device__ float  g_tw[Bn * Kn];
__device__ float  g_gl[Bn];     // latent . write_gate_w[0:H]
__device__ float  g_gd[Bn];     // latent . dmd_proj_w[0:H]
__device__ float  g_gp[Bn];     // latent . phase_proj_w  (complete)
__device__ int    g_lg_done;    // logits completion counter

// ---------------------------------------------------------------------------
// K1: query/value GEMM with packed f32x2 FMA (+ gate partials).
// Also resets g_lg_done (qv -> logits edge is fully serialized).
// ---------------------------------------------------------------------------
__global__ __launch_bounds__(256, 3)
void qv_kernel(const float* __restrict__ latent,
               const float* __restrict__ Wq, const float* __restrict__ bq,
               const float* __restrict__ Wv, const float* __restrict__ bv,
               const float* __restrict__ wg, const float* __restrict__ wd,
               const float* __restrict__ wp)
{
    __shared__ __align__(16) float4 smem[1024];   // 16 KB

    if (blockIdx.x == 0 && blockIdx.y == 0 && threadIdx.x == 0) g_lg_done = 0;

    const int b0 = blockIdx.x * 4;
    const int mat = blockIdx.y;
    const ulonglong2* W2 = (const ulonglong2*)(mat ? Wv : Wq);
    const float4* bias4  = (const float4*)(mat ? bv : bq);
    float4*       out4   = mat ? g_value : g_query;

    const int tid = threadIdx.x;
    const int dq  = tid & 31;
    const int hs  = tid >> 5;

    {
        const float4* src = (const float4*)(latent + (size_t)b0 * Hn);
        #pragma unroll
        for (int i = 0; i < 4; i++) smem[tid + i * 256] = src[tid + i * 256];
    }
    __syncthreads();

    u64 aLo[4], aHi[4];
    #pragma unroll
    for (int j = 0; j < 4; j++) { aLo[j] = 0ull; aHi[j] = 0ull; }

    const int hbase = hs * 128;
    #pragma unroll 4
    for (int c = 0; c < 32; c++) {
        const int h0 = hbase + c * 4;
        ulonglong2 w0 = W2[(size_t)(h0 + 0) * 32 + dq];
        ulonglong2 w1 = W2[(size_t)(h0 + 1) * 32 + dq];
        ulonglong2 w2 = W2[(size_t)(h0 + 2) * 32 + dq];
        ulonglong2 w3 = W2[(size_t)(h0 + 3) * 32 + dq];
        #pragma unroll
        for (int j = 0; j < 4; j++) {
            float4 lf = smem[j * 256 + hs * 32 + c];   // broadcast
            u64 lx = dup2(lf.x), ly = dup2(lf.y), lz = dup2(lf.z), lw = dup2(lf.w);
            aLo[j] = fma2(lx, w0.x, aLo[j]);
            aLo[j] = fma2(ly, w1.x, aLo[j]);
            aLo[j] = fma2(lz, w2.x, aLo[j]);
            aLo[j] = fma2(lw, w3.x, aLo[j]);
            aHi[j] = fma2(lx, w0.y, aHi[j]);
            aHi[j] = fma2(ly, w1.y, aHi[j]);
            aHi[j] = fma2(lz, w2.y, aHi[j]);
            aHi[j] = fma2(lw, w3.y, aHi[j]);
        }
    }

    if (mat == 0 && tid < 128) {
        const int wrp  = tid >> 5;
        const int lane = tid & 31;
        const float* latf = (const float*)smem + wrp * 1024;
        float pg = 0.f, pd = 0.f, pp = 0.f;
        #pragma unroll 8
        for (int i = lane; i < Hn; i += 32) {
            float x = latf[i];
            pg += x * wg[i];
            pd += x * wd[i];
            pp += x * wp[i];
        }
        #pragma unroll
        for (int o = 16; o; o >>= 1) {
            pg += __shfl_xor_sync(0xffffffffu, pg, o);
            pd += __shfl_xor_sync(0xffffffffu, pd, o);
            pp += __shfl_xor_sync(0xffffffffu, pp, o);
        }
        if (lane == 0) {
            g_gl[b0 + wrp] = pg;
            g_gd[b0 + wrp] = pd;
            g_gp[b0 + wrp] = pp;
        }
    }
    __syncthreads();

    #pragma unroll
    for (int j = 0; j < 4; j++) {
        float2 lo = unpack2(aLo[j]), hi = unpack2(aHi[j]);
        smem[hs * 128 + j * 32 + dq] = make_float4(lo.x, lo.y, hi.x, hi.y);
    }
    __syncthreads();

    if (tid < 128) {
        const int j2  = tid >> 5;
        const int dq2 = tid & 31;
        float4 s = make_float4(0.f, 0.f, 0.f, 0.f);
        #pragma unroll
        for (int h = 0; h < 8; h++) {
            float4 v = smem[h * 128 + j2 * 32 + dq2];
            s.x += v.x; s.y += v.y; s.z += v.z; s.w += v.w;
        }
        float4 bb = bias4[dq2];
        s.x += bb.x; s.y += bb.y; s.z += bb.z; s.w += bb.w;
        out4[(size_t)(b0 + j2) * 32 + dq2] = s;
    }
}

// ---------------------------------------------------------------------------
// K2: logits = query @ key^T, packed f32x2. Fires launch_dependents at START
// (releases batch early); publishes completion via g_lg_done at the end.
// ---------------------------------------------------------------------------
#define L_SMEM_BYTES ((32 + 64) * 33 * (int)sizeof(float4))

__global__ __launch_bounds__(256, 2)
void logits_kernel(const float* __restrict__ key)
{
    asm volatile("griddepcontrol.launch_dependents;");   // release batch now

    extern __shared__ float4 dyn[];
    float4* qs = dyn;             // [32][33]
    float4* ks = dyn + 32 * 33;   // [64][33]

    const int b0 = blockIdx.x * 32;
    const int s0 = blockIdx.y * 64;
    const int tid = threadIdx.x;

    const float4* q4 = g_query;
    const float4* k4 = (const float4*)key;
    #pragma unroll
    for (int i = tid; i < 32 * 32; i += 256) {
        int r = i >> 5, c = i & 31;
        qs[r * 33 + c] = q4[(size_t)(b0 + r) * 32 + c];
    }
    #pragma unroll
    for (int i = tid; i < 64 * 32; i += 256) {
        int r = i >> 5, c = i & 31;
        ks[r * 33 + c] = k4[(size_t)(s0 + r) * 32 + c];
    }
    __syncthreads();

    const ulonglong2* qs2 = (const ulonglong2*)qs;
    const ulonglong2* ks2 = (const ulonglong2*)ks;

    const int tx = tid & 15;
    const int ty = tid >> 4;

    u64 accp[2][4];
    #pragma unroll
    for (int i = 0; i < 2; i++)
        #pragma unroll
        for (int j = 0; j < 4; j++) accp[i][j] = 0ull;

    #pragma unroll 8
    for (int c = 0; c < 32; c++) {
        ulonglong2 qv2[2], kv2[4];
        #pragma unroll
        for (int i = 0; i < 2; i++) qv2[i] = qs2[(ty + 16 * i) * 33 + c];
        #pragma unroll
        for (int j = 0; j < 4; j++) kv2[j] = ks2[(tx + 16 * j) * 33 + c];
        #pragma unroll
        for (int i = 0; i < 2; i++)
            #pragma unroll
            for (int j = 0; j < 4; j++) {
                accp[i][j] = fma2(qv2[i].x, kv2[j].x, accp[i][j]);
                accp[i][j] = fma2(qv2[i].y, kv2[j].y, accp[i][j]);
            }
    }

    #pragma unroll
    for (int i = 0; i < 2; i++)
        #pragma unroll
        for (int j = 0; j < 4; j++) {
            float2 p = unpack2(accp[i][j]);
            g_logits[(size_t)(b0 + ty + 16 * i) * Sn + s0 + tx + 16 * j] = p.x + p.y;
        }

    // publish completion
    __threadfence();
    __syncthreads();
    if (tid == 0) atomicAdd(&g_lg_done, 1);
}

// ---------------------------------------------------------------------------
// K3 (PSS secondary of logits): fires launch_dependents FIRST (releases the
// copy at ~logits start), zeroes its weights row, spin-waits logits' flag,
// then top-32/softmax/read/gate. Stashes ti/tw for fixup.
// ---------------------------------------------------------------------------
__global__ __launch_bounds__(256, 4)
void batch_kernel(const float* __restrict__ memory,
                  const float* __restrict__ wg, const float* __restrict__ bg,
                  const float* __restrict__ wd, const float* __restrict__ bd,
                  const float* __restrict__ bp,
                  float* __restrict__ out)
{
    asm volatile("griddepcontrol.launch_dependents;");   // release the copy

    __shared__ __align__(16) float sl[Sn];
    __shared__ __align__(16) float rd[Dn];
    __shared__ int   s_flag;
    __shared__ int   ti[Kn];
    __shared__ float tw[Kn];

    const int b    = blockIdx.x;
    const int tid  = threadIdx.x;
    const int lane = tid & 31;

    // independent preamble: zero the weights row
    float* wout = out + W_OFF + (size_t)b * Sn;
    for (int i = tid; i < Sn / 4; i += 256)
        ((float4*)wout)[i] = make_float4(0.f, 0.f, 0.f, 0.f);

    // wait for logits completion (block-consistent double-barrier poll)
    for (;;) {
        if (tid == 0) s_flag = (atomicAdd(&g_lg_done, 0) >= (Bn / 32) * (Sn / 64));
        __syncthreads();
        int f = s_flag;
        __syncthreads();
        if (f) break;
        __nanosleep(100);
    }
    __threadfence();

    for (int i = tid; i < Sn; i += 256) sl[i] = g_logits[(size_t)b * Sn + i];
    __syncthreads();

    if (tid < 32) {
        for (int it = 0; it < Kn; it++) {
            float bv = -1e30f; int bi = 0;
            #pragma unroll
            for (int j = 0; j < 32; j++) {
                float v = sl[lane + 32 * j];
                if (v > bv) { bv = v; bi = lane + 32 * j; }
            }
            #pragma unroll
            for (int o = 16; o; o >>= 1) {
                float ov = __shfl_xor_sync(0xffffffffu, bv, o);
                int   oi = __shfl_xor_sync(0xffffffffu, bi, o);
                if (ov > bv || (ov == bv && oi < bi)) { bv = ov; bi = oi; }
            }
            if ((bi & 31) == lane) sl[bi] = -1e30f;
            if (lane == 0) { ti[it] = bi; tw[it] = bv; }
            __syncwarp();
        }
        float m = tw[0];
        float e = __expf(tw[lane] - m);
        float s = e;
        #pragma unroll
        for (int o = 16; o; o >>= 1) s += __shfl_xor_sync(0xffffffffu, s, o);
        float wgt = e / s;
        tw[lane] = wgt;
        g_ti[b * Kn + lane] = ti[lane];
        g_tw[b * Kn + lane] = wgt;
        __syncwarp();
    }
    __syncthreads();

    if (tid < Kn) wout[ti[tid]] = tw[tid];

    if (tid < Dn) {
        float acc = 0.f;
        #pragma unroll 8
        for (int k = 0; k < Kn; k++)
            acc += tw[k] * memory[((size_t)b * Sn + ti[k]) * Dn + tid];
        out[READ_OFF + (size_t)b * Dn + tid] = acc;
        rd[tid] = acc;
    }
    __syncthreads();

    if (tid < 32) {
        float4 x4 = ((const float4*)rd)[lane];
        const float4* wg4 = (const float4*)(wg + Hn);
        const float4* wd4 = (const float4*)(wd + Hn);
        float4 a = wg4[lane], d = wd4[lane];
        float pg = x4.x*a.x + x4.y*a.y + x4.z*a.z + x4.w*a.w;
        float pd = x4.x*d.x + x4.y*d.y + x4.z*d.z + x4.w*d.w;
        #pragma unroll
        for (int o = 16; o; o >>= 1) {
            pg += __shfl_xor_sync(0xffffffffu, pg, o);
            pd += __shfl_xor_sync(0xffffffffu, pd, o);
        }
        if (lane == 0) {
            float G  = g_gl[b] + pg;
            float Dv = g_gd[b] + pd;
            float P  = g_gp[b];
            float gate = 1.f / (1.f + __expf(-(G + bg[0])));
            float dmd  = tanhf(Dv + bd[0]);
            gate = gate * (0.75f + 0.5f * (dmd + 1.0f) * 0.5f);
            gate = fminf(fmaxf(gate, 0.f), 1.f);
            float ph = P + bp[0];
            gate *= 0.5f * (1.f + cosf(ph));
            g_gate[b] = gate;
        }
    }
}

// ---------------------------------------------------------------------------
// K4 (PSS secondary of batch): pure 256 MB streaming copy. Independent.
// ---------------------------------------------------------------------------
__global__ __launch_bounds__(256, 8)
void pure_copy_kernel(const float4* __restrict__ src, float4* __restrict__ dst)
{
    size_t base = (size_t)blockIdx.x * 1024 + threadIdx.x;
    #pragma unroll
    for (int j = 0; j < 4; j++) {
        size_t g = base + (size_t)j * 256;
        __stcs(&dst[g], __ldcs(&src[g]));
    }
}

// ---------------------------------------------------------------------------
// K5: blend the 32 top-k rows per batch. NORMAL launch: serializes after ALL
// prior stream work (batch and copy).
// ---------------------------------------------------------------------------
__global__ __launch_bounds__(256, 8)
void fixup_kernel(const float4* __restrict__ mem4, float* __restrict__ out)
{
    __shared__ int   ti[Kn];
    __shared__ float gw[Kn];

    const int b   = blockIdx.x;
    const int tid = threadIdx.x;

    if (tid < Kn) {
        ti[tid] = g_ti[b * Kn + tid];
        gw[tid] = g_gate[b] * g_tw[b * Kn + tid];
    }
    __syncthreads();

    float4* dst = (float4*)(out + MEM_OFF);

    #pragma unroll
    for (int i = 0; i < 4; i++) {
        int idx = tid + i * 256;          // 0..1023
        int r   = idx >> 5;               // topk slot
        int q   = idx & 31;               // quad in row
        int s   = ti[r];
        float w = gw[r];
        size_t g = ((size_t)b * Sn + s) * 32 + q;
        float4 m = mem4[g];
        float4 v = g_value[(size_t)b * 32 + q];
        m.x += w * (v.x - m.x);
        m.y += w * (v.y - m.y);
        m.z += w * (v.z - m.z);
        m.w += w * (v.w - m.w);
        dst[g] = m;
    }
}

// ---------------------------------------------------------------------------
extern "C" void kernel_launch(void* const* d_in, const int* in_sizes, int n_in,
                              void* d_out, int out_size)
{
    const float* latent    = (const float*)d_in[0];
    const float* memory    = (const float*)d_in[1];
    const float* rq_w      = (const float*)d_in[2];
    const float* rq_b      = (const float*)d_in[3];
    const float* mem_key   = (const float*)d_in[4];
    const float* wg_w      = (const float*)d_in[5];
    const float* wg_b      = (const float*)d_in[6];
    const float* wd_w      = (const float*)d_in[7];
    const float* wd_b      = (const float*)d_in[8];
    const float* wp_w      = (const float*)d_in[9];
    const float* wp_b      = (const float*)d_in[10];
    const float* wv_w      = (const float*)d_in[11];
    const float* wv_b      = (const float*)d_in[12];
    float* out = (float*)d_out;

    cudaFuncSetAttribute(logits_kernel,
                         cudaFuncAttributeMaxDynamicSharedMemorySize, L_SMEM_BYTES);

    qv_kernel<<<dim3(Bn / 4, 2), 256>>>(latent, rq_w, rq_b, wv_w, wv_b,
                                        wg_w, wd_w, wp_w);
    logits_kernel<<<dim3(Bn / 32, Sn / 64), 256, L_SMEM_BYTES>>>(mem_key);

    // batch: PSS secondary of logits (launches at logits' first instruction)
    {
        cudaLaunchConfig_t cfg = {};
        cfg.gridDim  = dim3(Bn);
        cfg.blockDim = dim3(256);
        cfg.stream = 0;
        cudaLaunchAttribute attr[1];
        attr[0].id = cudaLaunchAttributeProgrammaticStreamSerialization;
        attr[0].val.programmaticStreamSerializationAllowed = 1;
        cfg.attrs = attr;
        cfg.numAttrs = 1;
        cudaError_t e = cudaLaunchKernelEx(&cfg, batch_kernel, memory,
                                           wg_w, wg_b, wd_w, wd_b, wp_b, out);
        if (e != cudaSuccess)
            batch_kernel<<<Bn, 256>>>(memory, wg_w, wg_b, wd_w, wd_b, wp_b, out);
    }

    // copy: PSS secondary of batch (launches at batch's first instruction)
    {
        const float4* src = (const float4*)memory;
        float4*       dst = (float4*)(out + MEM_OFF);
        cudaLaunchConfig_t cfg = {};
        cfg.gridDim  = dim3((Bn * Sn * Dn / 4) / 1024);
        cfg.blockDim = dim3(256);
        cfg.stream = 0;
        cudaLaunchAttribute attr[1];
        attr[0].id = cudaLaunchAttributeProgrammaticStreamSerialization;
        attr[0].val.programmaticStreamSerializationAllowed = 1;
        cfg.attrs = attr;
        cfg.numAttrs = 1;
        cudaError_t e = cudaLaunchKernelEx(&cfg, pure_copy_kernel, src, dst);
        if (e != cudaSuccess)
            pure_copy_kernel<<<(Bn * Sn * Dn / 4) / 1024, 256>>>(src, dst);
    }

    fixup_kernel<<<Bn, 256>>>((const float4*)memory, out);
}